// round 15
// baseline (speedup 1.0000x reference)
#include <cuda_runtime.h>
#include <cuda_bf16.h>
#include <cuda_fp8.h>
#include <cstdint>

#define HIDDEN 768
#define UNITS  768

// ---------------- scratch (no allocation allowed) ----------------
__device__ __align__(16) uint8_t g_wT[(size_t)UNITS * HIDDEN];   // e4m3 transposed weight

// ---------------- fp8 quantize (E4M3, RNE, satfinite) ----------------
__device__ __forceinline__ uint8_t q8(float y) {
    return (uint8_t)__nv_cvt_float_to_fp8(y, __NV_SATFINITE, __NV_E4M3);
}

// ======================= Kernel 1: weight quantize + transpose =======================
__global__ void __launch_bounds__(256) wq_kernel(const float* __restrict__ w) {
    __shared__ uint8_t tile[32][33];
    int n0 = blockIdx.x * 32;
    int k0 = blockIdx.y * 32;
    int tx = threadIdx.x, ty = threadIdx.y;
#pragma unroll
    for (int i = ty; i < 32; i += 8)
        tile[i][tx] = q8(w[(size_t)(k0 + i) * UNITS + n0 + tx]);
    __syncthreads();
#pragma unroll
    for (int i = ty; i < 32; i += 8)
        g_wT[(size_t)(n0 + i) * HIDDEN + k0 + tx] = tile[tx][i];
}

// ======================= Kernel 2: fused LayerNorm + fp8 GEMM + bias =======================
#define BM 64
#define BN 128
#define NT (UNITS / BN)                 // 6
#define KCHUNK 128
#define NKC (HIDDEN / KCHUNK)           // 6
#define APAD 784                        // 784 mod 128 = 16 -> conflict-free LDSM
#define A_BYTES (BM * APAD)             // 50176
#define BROWPAD 144                     // 144 mod 128 = 16 -> conflict-free LDSM
#define BSTAGE_BYTES (BN * BROWPAD)     // 18432
#define NSTAGE 3
#define SMEM_TOTAL (A_BYTES + NSTAGE * BSTAGE_BYTES)   // 105472 -> occ 2

#define LDSM_X4(r0, r1, r2, r3, addr) \
    asm volatile("ldmatrix.sync.aligned.m8n8.x4.shared.b16 {%0,%1,%2,%3}, [%4];" \
                 : "=r"(r0), "=r"(r1), "=r"(r2), "=r"(r3) : "r"(addr))

#define MMA_E4M3(acc, a0, a1, a2, a3, b0, b1) \
    asm volatile( \
        "mma.sync.aligned.m16n8k32.row.col.f32.e4m3.e4m3.f32 " \
        "{%0,%1,%2,%3}, {%4,%5,%6,%7}, {%8,%9}, {%0,%1,%2,%3};" \
        : "+f"((acc)[0]), "+f"((acc)[1]), "+f"((acc)[2]), "+f"((acc)[3]) \
        : "r"(a0), "r"(a1), "r"(a2), "r"(a3), "r"(b0), "r"(b1))

__global__ void __launch_bounds__(256, 2) lngemm_kernel(
    const float* __restrict__ x,
    const float* __restrict__ gamma,
    const float* __restrict__ beta,
    const float* __restrict__ bias,
    float* __restrict__ out)
{
    extern __shared__ uint8_t smem[];
    const uint32_t sb = (uint32_t)__cvta_generic_to_shared(smem);

    const int tid  = threadIdx.x;
    const int lane = tid & 31;
    const int wid  = tid >> 5;
    const int wm   = wid & 1;        // 0..1 -> 32 M rows each
    const int wn   = wid >> 1;       // 0..3 -> 32 N cols each
    const int m0   = blockIdx.x * BM;

    // ---- hoisted per-thread cp.async addressing ----
    // thread covers rows (tid>>3) + {0,32,64,96}, 16B segment (tid&7)
    const int    pf_row  = tid >> 3;
    const int    pf_col  = (tid & 7) * 16;
    const size_t pf_gbase = (size_t)pf_row * HIDDEN + pf_col;
    const uint32_t pf_sbase = sb + (uint32_t)A_BYTES + (uint32_t)(pf_row * BROWPAD + pf_col);

    auto prefetchB = [&](const uint8_t* Bg, int kc) {
        const uint8_t* gp = Bg + pf_gbase + (size_t)kc * KCHUNK;
        uint32_t sp = pf_sbase + (uint32_t)(kc % NSTAGE) * BSTAGE_BYTES;
#pragma unroll
        for (int h = 0; h < 4; h++) {
            asm volatile("cp.async.cg.shared.global [%0], [%1], 16;"
                         :: "r"(sp + (uint32_t)(h * 32 * BROWPAD)),
                            "l"(gp + (size_t)h * 32 * HIDDEN));
        }
        asm volatile("cp.async.commit_group;");
    };

    // kick off first N-tile's B pipeline BEFORE LN so loads overlap LN compute
    prefetchB(g_wT, 0);
    prefetchB(g_wT, 1);

    // ---- Phase 1: LayerNorm 64 rows -> e4m3 into A smem ----
    {
        const float inv_h = 1.0f / (float)HIDDEN;
#pragma unroll 1
        for (int i = 0; i < 8; i++) {
            int lr  = wid * 8 + i;
            const float4* xr = reinterpret_cast<const float4*>(x + (size_t)(m0 + lr) * HIDDEN);
            float4 v[6];
            float sum = 0.f, sq = 0.f;
#pragma unroll
            for (int j = 0; j < 6; j++) {
                v[j] = __ldcs(&xr[lane + 32 * j]);
                sum += (v[j].x + v[j].y) + (v[j].z + v[j].w);
                sq  += (v[j].x * v[j].x + v[j].y * v[j].y) + (v[j].z * v[j].z + v[j].w * v[j].w);
            }
#pragma unroll
            for (int o = 16; o > 0; o >>= 1) {
                sum += __shfl_xor_sync(0xffffffffu, sum, o);
                sq  += __shfl_xor_sync(0xffffffffu, sq,  o);
            }
            float mu  = sum * inv_h;
            float var = fmaxf(sq * inv_h - mu * mu, 0.0f);
            float rs  = rsqrtf(var + 1e-5f);
#pragma unroll
            for (int j = 0; j < 6; j++) {
                int c = (lane + 32 * j) * 4;
                float4 g4 = *reinterpret_cast<const float4*>(gamma + c);
                float4 b4 = *reinterpret_cast<const float4*>(beta + c);
                uint32_t p0 = q8((v[j].x - mu) * rs * g4.x + b4.x);
                uint32_t p1 = q8((v[j].y - mu) * rs * g4.y + b4.y);
                uint32_t p2 = q8((v[j].z - mu) * rs * g4.z + b4.z);
                uint32_t p3 = q8((v[j].w - mu) * rs * g4.w + b4.w);
                *reinterpret_cast<uint32_t*>(smem + lr * APAD + c) =
                    p0 | (p1 << 8) | (p2 << 16) | (p3 << 24);
            }
        }
    }
    __syncthreads();

    // ---- per-lane ldmatrix base addresses ----
    uint32_t a_base[2];
    {
        int r   = wm * 32 + (lane & 7) + 8 * ((lane >> 3) & 1);
        int byo = 16 * (lane >> 4);
#pragma unroll
        for (int f = 0; f < 2; f++)
            a_base[f] = sb + (uint32_t)((r + f * 16) * APAD + byo);
    }
    uint32_t b_base[2];
    {
        int nrow = wn * 32 + ((lane >> 4) * 8) + (lane & 7);
        int byo  = 16 * ((lane >> 3) & 1);
#pragma unroll
        for (int p = 0; p < 2; p++)
            b_base[p] = sb + (uint32_t)(A_BYTES + (nrow + p * 16) * BROWPAD + byo);
    }

    const int rq = lane >> 2;

    // ---- Phase 2: loop over 6 N-tiles ----
#pragma unroll 1
    for (int nt = 0; nt < NT; nt++) {
        const uint8_t* Bg = g_wT + (size_t)(nt * BN) * HIDDEN;

        float acc[2][4][4];
#pragma unroll
        for (int f = 0; f < 2; f++)
#pragma unroll
            for (int g = 0; g < 4; g++)
#pragma unroll
                for (int c = 0; c < 4; c++) acc[f][g][c] = 0.f;

        // ping-pong fragment buffers (no copies; compiler renames)
        uint32_t aF[2][8], bF[2][8];
        auto loadFrags = [&](int buf, uint32_t ka, uint32_t kb) {
            LDSM_X4(aF[buf][0], aF[buf][1], aF[buf][2], aF[buf][3], a_base[0] + ka);
            LDSM_X4(aF[buf][4], aF[buf][5], aF[buf][6], aF[buf][7], a_base[1] + ka);
            LDSM_X4(bF[buf][0], bF[buf][1], bF[buf][2], bF[buf][3], b_base[0] + kb);
            LDSM_X4(bF[buf][4], bF[buf][5], bF[buf][6], bF[buf][7], b_base[1] + kb);
        };
        auto mmaBlock = [&](int buf) {
#pragma unroll
            for (int f = 0; f < 2; f++) {
                MMA_E4M3(acc[f][0], aF[buf][4*f], aF[buf][4*f+1], aF[buf][4*f+2], aF[buf][4*f+3],
                         bF[buf][0], bF[buf][1]);
                MMA_E4M3(acc[f][1], aF[buf][4*f], aF[buf][4*f+1], aF[buf][4*f+2], aF[buf][4*f+3],
                         bF[buf][2], bF[buf][3]);
                MMA_E4M3(acc[f][2], aF[buf][4*f], aF[buf][4*f+1], aF[buf][4*f+2], aF[buf][4*f+3],
                         bF[buf][4], bF[buf][5]);
                MMA_E4M3(acc[f][3], aF[buf][4*f], aF[buf][4*f+1], aF[buf][4*f+2], aF[buf][4*f+3],
                         bF[buf][6], bF[buf][7]);
            }
        };

#pragma unroll 1
        for (int kc = 0; kc < NKC; kc++) {
            if (kc < NKC - 1) asm volatile("cp.async.wait_group 1;" ::: "memory");
            else              asm volatile("cp.async.wait_group 0;" ::: "memory");
            __syncthreads();
            if (kc + 2 < NKC) prefetchB(Bg, kc + 2);

            const uint32_t soff = (uint32_t)(kc % NSTAGE) * BSTAGE_BYTES;
            const uint32_t aoff = (uint32_t)(kc * KCHUNK);

            loadFrags(0, aoff,      soff);
            loadFrags(1, aoff + 32, soff + 32);
            mmaBlock(0);
            loadFrags(0, aoff + 64, soff + 64);
            mmaBlock(1);
            loadFrags(1, aoff + 96, soff + 96);
            mmaBlock(0);
            mmaBlock(1);

            // overlap next tile's first loads with this tile's epilogue
            if (kc == NKC - 1 && nt + 1 < NT) {
                const uint8_t* Bg2 = g_wT + (size_t)((nt + 1) * BN) * HIDDEN;
                prefetchB(Bg2, 0);
                prefetchB(Bg2, 1);
            }
        }

        // ---- epilogue for this N-tile: bias add, direct stores ----
        {
            const int mrow  = m0 + wm * 32 + rq;
            const int ncol0 = nt * BN + wn * 32 + (lane & 3) * 2;
#pragma unroll
            for (int g = 0; g < 4; g++) {
                int c = ncol0 + g * 8;
                float bx = __ldg(bias + c);
                float by = __ldg(bias + c + 1);
#pragma unroll
                for (int f = 0; f < 2; f++) {
                    int r0 = mrow + f * 16;
                    float2 v0 = make_float2(acc[f][g][0] + bx, acc[f][g][1] + by);
                    float2 v1 = make_float2(acc[f][g][2] + bx, acc[f][g][3] + by);
                    *reinterpret_cast<float2*>(out + (size_t)r0 * UNITS + c)       = v0;
                    *reinterpret_cast<float2*>(out + (size_t)(r0 + 8) * UNITS + c) = v1;
                }
            }
        }
    }
}

// ======================= launch =======================
extern "C" void kernel_launch(void* const* d_in, const int* in_sizes, int n_in,
                              void* d_out, int out_size) {
    const float* x      = (const float*)d_in[0];
    const float* gamma  = (const float*)d_in[1];
    const float* beta   = (const float*)d_in[2];
    const float* kernel = (const float*)d_in[3];
    const float* bias   = (const float*)d_in[4];
    float* out = (float*)d_out;

    int tokens = in_sizes[0] / HIDDEN;   // 65536

    wq_kernel<<<dim3(UNITS / 32, HIDDEN / 32), dim3(32, 8)>>>(kernel);

    static int smem_set = 0;
    if (!smem_set) {
        cudaFuncSetAttribute(lngemm_kernel, cudaFuncAttributeMaxDynamicSharedMemorySize, SMEM_TOTAL);
        smem_set = 1;
    }
    lngemm_kernel<<<tokens / BM, 256, SMEM_TOTAL>>>(x, gamma, beta, bias, out);
}

// round 16
// speedup vs baseline: 1.0055x; 1.0055x over previous
#include <cuda_runtime.h>
#include <cuda_bf16.h>
#include <cuda_fp8.h>
#include <cstdint>

#define HIDDEN 768
#define UNITS  768

// ---------------- scratch (no allocation allowed) ----------------
__device__ __align__(16) uint8_t g_wT[(size_t)UNITS * HIDDEN];   // e4m3 transposed weight

// ---------------- fp8 quantize (E4M3, RNE, satfinite) ----------------
__device__ __forceinline__ uint8_t q8(float y) {
    return (uint8_t)__nv_cvt_float_to_fp8(y, __NV_SATFINITE, __NV_E4M3);
}

// ======================= Kernel 1: weight quantize + transpose =======================
__global__ void __launch_bounds__(256) wq_kernel(const float* __restrict__ w) {
    __shared__ uint8_t tile[32][33];
    int n0 = blockIdx.x * 32;
    int k0 = blockIdx.y * 32;
    int tx = threadIdx.x, ty = threadIdx.y;
#pragma unroll
    for (int i = ty; i < 32; i += 8)
        tile[i][tx] = q8(w[(size_t)(k0 + i) * UNITS + n0 + tx]);
    __syncthreads();
#pragma unroll
    for (int i = ty; i < 32; i += 8)
        g_wT[(size_t)(n0 + i) * HIDDEN + k0 + tx] = tile[tx][i];
}

// ======================= Kernel 2: fused LayerNorm + fp8 GEMM + bias =======================
#define BM 64
#define BN 128
#define NT (UNITS / BN)                 // 6
#define KCHUNK 128
#define NKC (HIDDEN / KCHUNK)           // 6
#define APAD 784                        // 784 mod 128 = 16 -> conflict-free LDSM
#define A_BYTES (BM * APAD)             // 50176
#define BROWPAD 144                     // 144 mod 128 = 16 -> conflict-free LDSM
#define BSTAGE_BYTES (BN * BROWPAD)     // 18432
#define NSTAGE 3
#define SMEM_TOTAL (A_BYTES + NSTAGE * BSTAGE_BYTES)   // 105472 -> occ 2

#define LDSM_X4(r0, r1, r2, r3, addr) \
    asm volatile("ldmatrix.sync.aligned.m8n8.x4.shared.b16 {%0,%1,%2,%3}, [%4];" \
                 : "=r"(r0), "=r"(r1), "=r"(r2), "=r"(r3) : "r"(addr))

#define MMA_E4M3(acc, a0, a1, a2, a3, b0, b1) \
    asm volatile( \
        "mma.sync.aligned.m16n8k32.row.col.f32.e4m3.e4m3.f32 " \
        "{%0,%1,%2,%3}, {%4,%5,%6,%7}, {%8,%9}, {%0,%1,%2,%3};" \
        : "+f"((acc)[0]), "+f"((acc)[1]), "+f"((acc)[2]), "+f"((acc)[3]) \
        : "r"(a0), "r"(a1), "r"(a2), "r"(a3), "r"(b0), "r"(b1))

__global__ void __launch_bounds__(256, 2) lngemm_kernel(
    const float* __restrict__ x,
    const float* __restrict__ gamma,
    const float* __restrict__ beta,
    const float* __restrict__ bias,
    float* __restrict__ out)
{
    extern __shared__ uint8_t smem[];
    const uint32_t sb = (uint32_t)__cvta_generic_to_shared(smem);

    const int tid  = threadIdx.x;
    const int lane = tid & 31;
    const int wid  = tid >> 5;
    const int wm   = wid & 1;        // 0..1 -> 32 M rows each
    const int wn   = wid >> 1;       // 0..3 -> 32 N cols each
    const int m0   = blockIdx.x * BM;

    // ---- hoisted per-thread cp.async addressing ----
    // thread covers rows (tid>>3) + {0,32,64,96}, 16B segment (tid&7)
    const int    pf_row  = tid >> 3;
    const int    pf_col  = (tid & 7) * 16;
    const size_t pf_gbase = (size_t)pf_row * HIDDEN + pf_col;
    const uint32_t pf_sbase = sb + (uint32_t)A_BYTES + (uint32_t)(pf_row * BROWPAD + pf_col);

    auto prefetchB = [&](const uint8_t* Bg, int kc) {
        const uint8_t* gp = Bg + pf_gbase + (size_t)kc * KCHUNK;
        uint32_t sp = pf_sbase + (uint32_t)(kc % NSTAGE) * BSTAGE_BYTES;
#pragma unroll
        for (int h = 0; h < 4; h++) {
            asm volatile("cp.async.cg.shared.global [%0], [%1], 16;"
                         :: "r"(sp + (uint32_t)(h * 32 * BROWPAD)),
                            "l"(gp + (size_t)h * 32 * HIDDEN));
        }
        asm volatile("cp.async.commit_group;");
    };

    // kick off first N-tile's B pipeline BEFORE LN so loads overlap LN compute
    prefetchB(g_wT, 0);
    prefetchB(g_wT, 1);

    // ---- Phase 1: LayerNorm 64 rows -> e4m3 into A smem ----
    {
        const float inv_h = 1.0f / (float)HIDDEN;
#pragma unroll 1
        for (int i = 0; i < 8; i++) {
            int lr  = wid * 8 + i;
            const float4* xr = reinterpret_cast<const float4*>(x + (size_t)(m0 + lr) * HIDDEN);
            float4 v[6];
            float sum = 0.f, sq = 0.f;
#pragma unroll
            for (int j = 0; j < 6; j++) {
                v[j] = __ldcs(&xr[lane + 32 * j]);
                sum += (v[j].x + v[j].y) + (v[j].z + v[j].w);
                sq  += (v[j].x * v[j].x + v[j].y * v[j].y) + (v[j].z * v[j].z + v[j].w * v[j].w);
            }
#pragma unroll
            for (int o = 16; o > 0; o >>= 1) {
                sum += __shfl_xor_sync(0xffffffffu, sum, o);
                sq  += __shfl_xor_sync(0xffffffffu, sq,  o);
            }
            float mu  = sum * inv_h;
            float var = fmaxf(sq * inv_h - mu * mu, 0.0f);
            float rs  = rsqrtf(var + 1e-5f);
#pragma unroll
            for (int j = 0; j < 6; j++) {
                int c = (lane + 32 * j) * 4;
                float4 g4 = *reinterpret_cast<const float4*>(gamma + c);
                float4 b4 = *reinterpret_cast<const float4*>(beta + c);
                uint32_t p0 = q8((v[j].x - mu) * rs * g4.x + b4.x);
                uint32_t p1 = q8((v[j].y - mu) * rs * g4.y + b4.y);
                uint32_t p2 = q8((v[j].z - mu) * rs * g4.z + b4.z);
                uint32_t p3 = q8((v[j].w - mu) * rs * g4.w + b4.w);
                *reinterpret_cast<uint32_t*>(smem + lr * APAD + c) =
                    p0 | (p1 << 8) | (p2 << 16) | (p3 << 24);
            }
        }
    }
    __syncthreads();

    // ---- per-lane ldmatrix base addresses ----
    uint32_t a_base[2];
    {
        int r   = wm * 32 + (lane & 7) + 8 * ((lane >> 3) & 1);
        int byo = 16 * (lane >> 4);
#pragma unroll
        for (int f = 0; f < 2; f++)
            a_base[f] = sb + (uint32_t)((r + f * 16) * APAD + byo);
    }
    uint32_t b_base[2];
    {
        int nrow = wn * 32 + ((lane >> 4) * 8) + (lane & 7);
        int byo  = 16 * ((lane >> 3) & 1);
#pragma unroll
        for (int p = 0; p < 2; p++)
            b_base[p] = sb + (uint32_t)(A_BYTES + (nrow + p * 16) * BROWPAD + byo);
    }

    const int rq = lane >> 2;

    // ---- Phase 2: loop over 6 N-tiles ----
#pragma unroll 1
    for (int nt = 0; nt < NT; nt++) {
        const uint8_t* Bg = g_wT + (size_t)(nt * BN) * HIDDEN;

        float acc[2][4][4];
#pragma unroll
        for (int f = 0; f < 2; f++)
#pragma unroll
            for (int g = 0; g < 4; g++)
#pragma unroll
                for (int c = 0; c < 4; c++) acc[f][g][c] = 0.f;

        // ping-pong fragment buffers (no copies; compiler renames)
        uint32_t aF[2][8], bF[2][8];
        auto loadFrags = [&](int buf, uint32_t ka, uint32_t kb) {
            LDSM_X4(aF[buf][0], aF[buf][1], aF[buf][2], aF[buf][3], a_base[0] + ka);
            LDSM_X4(aF[buf][4], aF[buf][5], aF[buf][6], aF[buf][7], a_base[1] + ka);
            LDSM_X4(bF[buf][0], bF[buf][1], bF[buf][2], bF[buf][3], b_base[0] + kb);
            LDSM_X4(bF[buf][4], bF[buf][5], bF[buf][6], bF[buf][7], b_base[1] + kb);
        };
        auto mmaBlock = [&](int buf) {
#pragma unroll
            for (int f = 0; f < 2; f++) {
                MMA_E4M3(acc[f][0], aF[buf][4*f], aF[buf][4*f+1], aF[buf][4*f+2], aF[buf][4*f+3],
                         bF[buf][0], bF[buf][1]);
                MMA_E4M3(acc[f][1], aF[buf][4*f], aF[buf][4*f+1], aF[buf][4*f+2], aF[buf][4*f+3],
                         bF[buf][2], bF[buf][3]);
                MMA_E4M3(acc[f][2], aF[buf][4*f], aF[buf][4*f+1], aF[buf][4*f+2], aF[buf][4*f+3],
                         bF[buf][4], bF[buf][5]);
                MMA_E4M3(acc[f][3], aF[buf][4*f], aF[buf][4*f+1], aF[buf][4*f+2], aF[buf][4*f+3],
                         bF[buf][6], bF[buf][7]);
            }
        };

#pragma unroll 1
        for (int kc = 0; kc < NKC; kc++) {
            if (kc < NKC - 1) asm volatile("cp.async.wait_group 1;" ::: "memory");
            else              asm volatile("cp.async.wait_group 0;" ::: "memory");
            __syncthreads();
            if (kc + 2 < NKC) prefetchB(Bg, kc + 2);

            const uint32_t soff = (uint32_t)(kc % NSTAGE) * BSTAGE_BYTES;
            const uint32_t aoff = (uint32_t)(kc * KCHUNK);

            loadFrags(0, aoff,      soff);
            loadFrags(1, aoff + 32, soff + 32);
            mmaBlock(0);
            loadFrags(0, aoff + 64, soff + 64);
            mmaBlock(1);
            loadFrags(1, aoff + 96, soff + 96);
            mmaBlock(0);
            mmaBlock(1);

            // overlap next tile's first loads with this tile's epilogue
            if (kc == NKC - 1 && nt + 1 < NT) {
                const uint8_t* Bg2 = g_wT + (size_t)((nt + 1) * BN) * HIDDEN;
                prefetchB(Bg2, 0);
                prefetchB(Bg2, 1);
            }
        }

        // ---- epilogue for this N-tile: bias add, direct stores ----
        {
            const int mrow  = m0 + wm * 32 + rq;
            const int ncol0 = nt * BN + wn * 32 + (lane & 3) * 2;
#pragma unroll
            for (int g = 0; g < 4; g++) {
                int c = ncol0 + g * 8;
                float bx = __ldg(bias + c);
                float by = __ldg(bias + c + 1);
#pragma unroll
                for (int f = 0; f < 2; f++) {
                    int r0 = mrow + f * 16;
                    float2 v0 = make_float2(acc[f][g][0] + bx, acc[f][g][1] + by);
                    float2 v1 = make_float2(acc[f][g][2] + bx, acc[f][g][3] + by);
                    *reinterpret_cast<float2*>(out + (size_t)r0 * UNITS + c)       = v0;
                    *reinterpret_cast<float2*>(out + (size_t)(r0 + 8) * UNITS + c) = v1;
                }
            }
        }
    }
}

// ======================= launch =======================
extern "C" void kernel_launch(void* const* d_in, const int* in_sizes, int n_in,
                              void* d_out, int out_size) {
    const float* x      = (const float*)d_in[0];
    const float* gamma  = (const float*)d_in[1];
    const float* beta   = (const float*)d_in[2];
    const float* kernel = (const float*)d_in[3];
    const float* bias   = (const float*)d_in[4];
    float* out = (float*)d_out;

    int tokens = in_sizes[0] / HIDDEN;   // 65536

    wq_kernel<<<dim3(UNITS / 32, HIDDEN / 32), dim3(32, 8)>>>(kernel);

    static int smem_set = 0;
    if (!smem_set) {
        cudaFuncSetAttribute(lngemm_kernel, cudaFuncAttributeMaxDynamicSharedMemorySize, SMEM_TOTAL);
        smem_set = 1;
    }
    lngemm_kernel<<<tokens / BM, 256, SMEM_TOTAL>>>(x, gamma, beta, bias, out);
}

// round 17
// speedup vs baseline: 1.0071x; 1.0016x over previous
#include <cuda_runtime.h>
#include <cuda_bf16.h>
#include <cuda_fp8.h>
#include <cstdint>

#define HIDDEN 768
#define UNITS  768

// ---------------- scratch (no allocation allowed) ----------------
__device__ __align__(16) uint8_t g_wT[(size_t)UNITS * HIDDEN];   // e4m3 transposed weight

// ---------------- fp8 quantize (E4M3, RNE, satfinite) ----------------
__device__ __forceinline__ uint8_t q8(float y) {
    return (uint8_t)__nv_cvt_float_to_fp8(y, __NV_SATFINITE, __NV_E4M3);
}

// ======================= Kernel 1: weight quantize + transpose =======================
__global__ void __launch_bounds__(256) wq_kernel(const float* __restrict__ w) {
    __shared__ uint8_t tile[32][33];
    int n0 = blockIdx.x * 32;
    int k0 = blockIdx.y * 32;
    int tx = threadIdx.x, ty = threadIdx.y;
#pragma unroll
    for (int i = ty; i < 32; i += 8)
        tile[i][tx] = q8(w[(size_t)(k0 + i) * UNITS + n0 + tx]);
    __syncthreads();
#pragma unroll
    for (int i = ty; i < 32; i += 8)
        g_wT[(size_t)(n0 + i) * HIDDEN + k0 + tx] = tile[tx][i];
}

// ======================= Kernel 2: fused LayerNorm + fp8 GEMM + bias =======================
#define BM 64
#define BN 128
#define NT (UNITS / BN)                 // 6
#define KCHUNK 128
#define NKC (HIDDEN / KCHUNK)           // 6
#define APAD 784                        // 784 mod 128 = 16 -> conflict-free LDSM
#define A_BYTES (BM * APAD)             // 50176
#define BROWPAD 144                     // 144 mod 128 = 16 -> conflict-free LDSM
#define BSTAGE_BYTES (BN * BROWPAD)     // 18432
#define NSTAGE 3
#define SMEM_TOTAL (A_BYTES + NSTAGE * BSTAGE_BYTES)   // 105472 -> occ 2

#define LDSM_X4(r0, r1, r2, r3, addr) \
    asm volatile("ldmatrix.sync.aligned.m8n8.x4.shared.b16 {%0,%1,%2,%3}, [%4];" \
                 : "=r"(r0), "=r"(r1), "=r"(r2), "=r"(r3) : "r"(addr))

#define MMA_E4M3(acc, a0, a1, a2, a3, b0, b1) \
    asm volatile( \
        "mma.sync.aligned.m16n8k32.row.col.f32.e4m3.e4m3.f32 " \
        "{%0,%1,%2,%3}, {%4,%5,%6,%7}, {%8,%9}, {%0,%1,%2,%3};" \
        : "+f"((acc)[0]), "+f"((acc)[1]), "+f"((acc)[2]), "+f"((acc)[3]) \
        : "r"(a0), "r"(a1), "r"(a2), "r"(a3), "r"(b0), "r"(b1))

__global__ void __launch_bounds__(256, 2) lngemm_kernel(
    const float* __restrict__ x,
    const float* __restrict__ gamma,
    const float* __restrict__ beta,
    const float* __restrict__ bias,
    float* __restrict__ out)
{
    extern __shared__ uint8_t smem[];
    const uint32_t sb = (uint32_t)__cvta_generic_to_shared(smem);

    const int tid  = threadIdx.x;
    const int lane = tid & 31;
    const int wid  = tid >> 5;
    const int wm   = wid & 1;        // 0..1 -> 32 M rows each
    const int wn   = wid >> 1;       // 0..3 -> 32 N cols each
    const int m0   = blockIdx.x * BM;

    // ---- hoisted per-thread cp.async addressing ----
    // thread covers rows (tid>>3) + {0,32,64,96}, 16B segment (tid&7)
    const int    pf_row  = tid >> 3;
    const int    pf_col  = (tid & 7) * 16;
    const size_t pf_gbase = (size_t)pf_row * HIDDEN + pf_col;
    const uint32_t pf_sbase = sb + (uint32_t)A_BYTES + (uint32_t)(pf_row * BROWPAD + pf_col);

    auto prefetchB = [&](const uint8_t* Bg, int kc) {
        const uint8_t* gp = Bg + pf_gbase + (size_t)kc * KCHUNK;
        uint32_t sp = pf_sbase + (uint32_t)(kc % NSTAGE) * BSTAGE_BYTES;
#pragma unroll
        for (int h = 0; h < 4; h++) {
            asm volatile("cp.async.cg.shared.global [%0], [%1], 16;"
                         :: "r"(sp + (uint32_t)(h * 32 * BROWPAD)),
                            "l"(gp + (size_t)h * 32 * HIDDEN));
        }
        asm volatile("cp.async.commit_group;");
    };

    // kick off first N-tile's B pipeline BEFORE LN so loads overlap LN compute
    prefetchB(g_wT, 0);
    prefetchB(g_wT, 1);

    // ---- Phase 1: LayerNorm 64 rows -> e4m3 into A smem ----
    {
        const float inv_h = 1.0f / (float)HIDDEN;
#pragma unroll 1
        for (int i = 0; i < 8; i++) {
            int lr  = wid * 8 + i;
            const float4* xr = reinterpret_cast<const float4*>(x + (size_t)(m0 + lr) * HIDDEN);
            float4 v[6];
            float sum = 0.f, sq = 0.f;
#pragma unroll
            for (int j = 0; j < 6; j++) {
                v[j] = __ldcs(&xr[lane + 32 * j]);
                sum += (v[j].x + v[j].y) + (v[j].z + v[j].w);
                sq  += (v[j].x * v[j].x + v[j].y * v[j].y) + (v[j].z * v[j].z + v[j].w * v[j].w);
            }
#pragma unroll
            for (int o = 16; o > 0; o >>= 1) {
                sum += __shfl_xor_sync(0xffffffffu, sum, o);
                sq  += __shfl_xor_sync(0xffffffffu, sq,  o);
            }
            float mu  = sum * inv_h;
            float var = fmaxf(sq * inv_h - mu * mu, 0.0f);
            float rs  = rsqrtf(var + 1e-5f);
#pragma unroll
            for (int j = 0; j < 6; j++) {
                int c = (lane + 32 * j) * 4;
                float4 g4 = *reinterpret_cast<const float4*>(gamma + c);
                float4 b4 = *reinterpret_cast<const float4*>(beta + c);
                uint32_t p0 = q8((v[j].x - mu) * rs * g4.x + b4.x);
                uint32_t p1 = q8((v[j].y - mu) * rs * g4.y + b4.y);
                uint32_t p2 = q8((v[j].z - mu) * rs * g4.z + b4.z);
                uint32_t p3 = q8((v[j].w - mu) * rs * g4.w + b4.w);
                *reinterpret_cast<uint32_t*>(smem + lr * APAD + c) =
                    p0 | (p1 << 8) | (p2 << 16) | (p3 << 24);
            }
        }
    }
    __syncthreads();

    // ---- per-lane ldmatrix base addresses ----
    uint32_t a_base[2];
    {
        int r   = wm * 32 + (lane & 7) + 8 * ((lane >> 3) & 1);
        int byo = 16 * (lane >> 4);
#pragma unroll
        for (int f = 0; f < 2; f++)
            a_base[f] = sb + (uint32_t)((r + f * 16) * APAD + byo);
    }
    uint32_t b_base[2];
    {
        int nrow = wn * 32 + ((lane >> 4) * 8) + (lane & 7);
        int byo  = 16 * ((lane >> 3) & 1);
#pragma unroll
        for (int p = 0; p < 2; p++)
            b_base[p] = sb + (uint32_t)(A_BYTES + (nrow + p * 16) * BROWPAD + byo);
    }

    const int rq = lane >> 2;

    // ---- Phase 2: loop over 6 N-tiles ----
#pragma unroll 1
    for (int nt = 0; nt < NT; nt++) {
        const uint8_t* Bg = g_wT + (size_t)(nt * BN) * HIDDEN;

        float acc[2][4][4];
#pragma unroll
        for (int f = 0; f < 2; f++)
#pragma unroll
            for (int g = 0; g < 4; g++)
#pragma unroll
                for (int c = 0; c < 4; c++) acc[f][g][c] = 0.f;

        // ping-pong fragment buffers (no copies; compiler renames)
        uint32_t aF[2][8], bF[2][8];
        auto loadFrags = [&](int buf, uint32_t ka, uint32_t kb) {
            LDSM_X4(aF[buf][0], aF[buf][1], aF[buf][2], aF[buf][3], a_base[0] + ka);
            LDSM_X4(aF[buf][4], aF[buf][5], aF[buf][6], aF[buf][7], a_base[1] + ka);
            LDSM_X4(bF[buf][0], bF[buf][1], bF[buf][2], bF[buf][3], b_base[0] + kb);
            LDSM_X4(bF[buf][4], bF[buf][5], bF[buf][6], bF[buf][7], b_base[1] + kb);
        };
        auto mmaBlock = [&](int buf) {
#pragma unroll
            for (int f = 0; f < 2; f++) {
                MMA_E4M3(acc[f][0], aF[buf][4*f], aF[buf][4*f+1], aF[buf][4*f+2], aF[buf][4*f+3],
                         bF[buf][0], bF[buf][1]);
                MMA_E4M3(acc[f][1], aF[buf][4*f], aF[buf][4*f+1], aF[buf][4*f+2], aF[buf][4*f+3],
                         bF[buf][2], bF[buf][3]);
                MMA_E4M3(acc[f][2], aF[buf][4*f], aF[buf][4*f+1], aF[buf][4*f+2], aF[buf][4*f+3],
                         bF[buf][4], bF[buf][5]);
                MMA_E4M3(acc[f][3], aF[buf][4*f], aF[buf][4*f+1], aF[buf][4*f+2], aF[buf][4*f+3],
                         bF[buf][6], bF[buf][7]);
            }
        };

#pragma unroll 1
        for (int kc = 0; kc < NKC; kc++) {
            if (kc < NKC - 1) asm volatile("cp.async.wait_group 1;" ::: "memory");
            else              asm volatile("cp.async.wait_group 0;" ::: "memory");
            __syncthreads();
            if (kc + 2 < NKC) prefetchB(Bg, kc + 2);

            const uint32_t soff = (uint32_t)(kc % NSTAGE) * BSTAGE_BYTES;
            const uint32_t aoff = (uint32_t)(kc * KCHUNK);

            loadFrags(0, aoff,      soff);
            loadFrags(1, aoff + 32, soff + 32);
            mmaBlock(0);
            loadFrags(0, aoff + 64, soff + 64);
            mmaBlock(1);
            loadFrags(1, aoff + 96, soff + 96);
            mmaBlock(0);
            mmaBlock(1);

            // overlap next tile's first loads with this tile's epilogue
            if (kc == NKC - 1 && nt + 1 < NT) {
                const uint8_t* Bg2 = g_wT + (size_t)((nt + 1) * BN) * HIDDEN;
                prefetchB(Bg2, 0);
                prefetchB(Bg2, 1);
            }
        }

        // ---- epilogue for this N-tile: bias add, direct stores ----
        {
            const int mrow  = m0 + wm * 32 + rq;
            const int ncol0 = nt * BN + wn * 32 + (lane & 3) * 2;
#pragma unroll
            for (int g = 0; g < 4; g++) {
                int c = ncol0 + g * 8;
                float bx = __ldg(bias + c);
                float by = __ldg(bias + c + 1);
#pragma unroll
                for (int f = 0; f < 2; f++) {
                    int r0 = mrow + f * 16;
                    float2 v0 = make_float2(acc[f][g][0] + bx, acc[f][g][1] + by);
                    float2 v1 = make_float2(acc[f][g][2] + bx, acc[f][g][3] + by);
                    *reinterpret_cast<float2*>(out + (size_t)r0 * UNITS + c)       = v0;
                    *reinterpret_cast<float2*>(out + (size_t)(r0 + 8) * UNITS + c) = v1;
                }
            }
        }
    }
}

// ======================= launch =======================
extern "C" void kernel_launch(void* const* d_in, const int* in_sizes, int n_in,
                              void* d_out, int out_size) {
    const float* x      = (const float*)d_in[0];
    const float* gamma  = (const float*)d_in[1];
    const float* beta   = (const float*)d_in[2];
    const float* kernel = (const float*)d_in[3];
    const float* bias   = (const float*)d_in[4];
    float* out = (float*)d_out;

    int tokens = in_sizes[0] / HIDDEN;   // 65536

    wq_kernel<<<dim3(UNITS / 32, HIDDEN / 32), dim3(32, 8)>>>(kernel);

    static int smem_set = 0;
    if (!smem_set) {
        cudaFuncSetAttribute(lngemm_kernel, cudaFuncAttributeMaxDynamicSharedMemorySize, SMEM_TOTAL);
        smem_set = 1;
    }
    lngemm_kernel<<<tokens / BM, 256, SMEM_TOTAL>>>(x, gamma, beta, bias, out);
}